// round 8
// baseline (speedup 1.0000x reference)
#include <cuda_runtime.h>
#include <cstdint>
#include <math.h>

// Problem constants (dataset: B=65536, D=256, K=10)
#define KK 10
#define DD 256
#define RPB 64                // rows per block (4 warps, 8 slots/warp, R=2)
#define FLAGCAP 65536
#define L2PI_F 1.8378770664093453f
#define MARGIN 0.03f

typedef unsigned long long ull;

// ---- device globals ----
__device__ int g_flag[FLAGCAP];   // 1 = row needs exact recompute (written every run)

// ---------- packed f32x2 helpers ----------
static __device__ __forceinline__ ull pack2(float x, float y) {
    ull r; asm("mov.b64 %0, {%1, %2};" : "=l"(r) : "f"(x), "f"(y)); return r;
}
static __device__ __forceinline__ void unpack2(ull v, float& x, float& y) {
    asm("mov.b64 {%0, %1}, %2;" : "=f"(x), "=f"(y) : "l"(v));
}
static __device__ __forceinline__ ull fma2(ull a, ull b, ull c) {
    ull d; asm("fma.rn.f32x2 %0, %1, %2, %3;" : "=l"(d) : "l"(a), "l"(b), "l"(c)); return d;
}
static __device__ __forceinline__ ull add2(ull a, ull b) {
    ull d; asm("add.rn.f32x2 %0, %1, %2;" : "=l"(d) : "l"(a), "l"(b)); return d;
}

// cheap finish for one row (tolerant path) — returns need-exact flag
static __device__ __forceinline__ int finish_row(
    const ull* acc, ull S2, const float* s_C, int row,
    float* out_logit, float* out_qy, float* out_ind)
{
    float s2f;
    { float lo, hi; unpack2(S2, lo, hi); s2f = lo + hi; }
    float l[KK];
    #pragma unroll
    for (int k = 0; k < KK; k++) {
        float lo, hi; unpack2(acc[k], lo, hi);
        l[k] = __fmaf_rn(-0.5f, (lo + hi) + s2f, s_C[k]);
    }
    float t1 = l[0], t2 = -3.4e38f;
    #pragma unroll
    for (int k = 1; k < KK; k++) {
        float v = l[k];
        if (v > t1) { t2 = t1; t1 = v; } else if (v > t2) t2 = v;
    }
    float e[KK], ssum = 0.0f;
    #pragma unroll
    for (int k = 0; k < KK; k++) { e[k] = __expf(l[k] - t1); ssum += e[k]; }
    float inv = 1.0f / ssum;

    float2* lo2 = reinterpret_cast<float2*>(out_logit + (size_t)row * KK);
    float2* qo2 = reinterpret_cast<float2*>(out_qy    + (size_t)row * KK);
    #pragma unroll
    for (int i = 0; i < KK / 2; i++) {
        lo2[i] = make_float2(l[2 * i], l[2 * i + 1]);
        qo2[i] = make_float2(e[2 * i] * inv, e[2 * i + 1] * inv);
    }
    int best = 0; float bv = l[0];
    #pragma unroll
    for (int k = 1; k < KK; k++) if (l[k] > bv) { bv = l[k]; best = k; }
    out_ind[row] = (float)best;
    return (t1 - t2 < MARGIN) ? 1 : 0;
}

// ================= kernel 1: prep-in-block + cheap logits (R=2) + finish + flags =====
__global__ void __launch_bounds__(128, 5)
k_main(const float* __restrict__ q, const float* __restrict__ mu,
       const float* __restrict__ lv,
       float* __restrict__ out_logit, float* __restrict__ out_qy,
       float* __restrict__ out_ind, int nrows)
{
    // coef table: ulonglong2 index ((2g+h)*5 + kp)*4 + s ; .x = k=2kp (d,d+1), .y = k=2kp+1
    __shared__ __align__(16) ulonglong2 s_cb[640];   // 10240 B
    __shared__ float s_Cpart[KK][8];
    __shared__ float s_C[KK];
    __shared__ int   s_nz;

    const int t = threadIdx.x;
    if (t == 0) s_nz = 0;
    __syncthreads();

    // ---- per-block prep (cheap, __expf; exact when lv==0 since EX2(0)=1) ----
    int any = 0;
    #pragma unroll
    for (int i = 0; i < 5; i++) {
        int e = t + 128 * i;            // 0..639
        int s  = e & 3;
        int rest = e >> 2;
        int kp = rest % 5;
        int gh = rest / 5;              // 0..31
        int h = gh & 1, g = gh >> 1;
        int pair = 8 * g + 2 * s + h, d = 2 * pair;
        int k0 = 2 * kp, k1 = 2 * kp + 1;
        float l00 = lv[k0 * DD + d], l01 = lv[k0 * DD + d + 1];
        float l10 = lv[k1 * DD + d], l11 = lv[k1 * DD + d + 1];
        float m00 = mu[k0 * DD + d], m01 = mu[k0 * DD + d + 1];
        float m10 = mu[k1 * DD + d], m11 = mu[k1 * DD + d + 1];
        ulonglong2 u;
        u.x = pack2(-2.0f * __expf(-l00) * m00, -2.0f * __expf(-l01) * m01);
        u.y = pack2(-2.0f * __expf(-l10) * m10, -2.0f * __expf(-l11) * m11);
        s_cb[e] = u;
        if (l00 != 0.0f || l01 != 0.0f || l10 != 0.0f || l11 != 0.0f) any = 1;
    }
    if (any) atomicOr(&s_nz, 1);
    if (t < 80) {
        int k = t >> 3, part = t & 7;
        float s = 0.0f;
        #pragma unroll 4
        for (int j = 0; j < 32; j++) {
            int d = part * 32 + j;
            float l = lv[k * DD + d], m = mu[k * DD + d];
            s += __fmaf_rn(__expf(-l) * m, m, l) + L2PI_F;
        }
        s_Cpart[k][part] = s;
    }
    __syncthreads();
    if (t < KK) {
        float tot = 0.0f;
        #pragma unroll
        for (int j = 0; j < 8; j++) tot += s_Cpart[t][j];
        float logk = (float)log((double)(1.0f / (float)KK));
        s_C[t] = __fmaf_rn(-0.5f, tot, logk);
    }
    __syncthreads();
    const int fast = (s_nz == 0);

    // ---- main loop: 4 threads/row, 2 rows/thread ----
    const int lane = t & 31, warp = t >> 5;
    const int s = lane & 3, r = lane >> 2;           // sub, row-slot
    const int rowA = blockIdx.x * RPB + warp * 16 + r;
    const int rowB = rowA + 8;
    const int cA = (rowA < nrows) ? rowA : 0;
    const int cB = (rowB < nrows) ? rowB : 0;
    const float4* qpA = reinterpret_cast<const float4*>(q) + (size_t)cA * 64 + s;
    const float4* qpB = reinterpret_cast<const float4*>(q) + (size_t)cB * 64 + s;

    ull accA[KK], accB[KK];
    #pragma unroll
    for (int k = 0; k < KK; k++) { accA[k] = 0ull; accB[k] = 0ull; }
    ull S2A = 0ull, S2B = 0ull;

    // depth-2 software pipeline, 4 LDG.128 in flight
    float4 pA0 = __ldg(qpA),     pB0 = __ldg(qpB);
    float4 pA1 = __ldg(qpA + 4), pB1 = __ldg(qpB + 4);

    #pragma unroll
    for (int g = 0; g < 16; g++) {
        float4 vA = pA0, vB = pB0;
        pA0 = pA1; pB0 = pB1;
        if (g + 2 < 16) {
            pA1 = __ldg(qpA + 4 * (g + 2));
            pB1 = __ldg(qpB + 4 * (g + 2));
        }
        ull qa0 = pack2(vA.x, vA.y), qa1 = pack2(vA.z, vA.w);
        ull qb0 = pack2(vB.x, vB.y), qb1 = pack2(vB.z, vB.w);
        S2A = fma2(qa0, qa0, S2A); S2A = fma2(qa1, qa1, S2A);
        S2B = fma2(qb0, qb0, S2B); S2B = fma2(qb1, qb1, S2B);

        const int b0 = (2 * g) * 20 + s;       // ((2g+h)*5+kp)*4+s, h=0
        const int b1 = (2 * g + 1) * 20 + s;   // h=1
        #pragma unroll
        for (int kp = 0; kp < 5; kp++) {
            ulonglong2 c0 = s_cb[b0 + 4 * kp];
            accA[2 * kp]     = fma2(c0.x, qa0, accA[2 * kp]);
            accA[2 * kp + 1] = fma2(c0.y, qa0, accA[2 * kp + 1]);
            accB[2 * kp]     = fma2(c0.x, qb0, accB[2 * kp]);
            accB[2 * kp + 1] = fma2(c0.y, qb0, accB[2 * kp + 1]);
            ulonglong2 c1 = s_cb[b1 + 4 * kp];
            accA[2 * kp]     = fma2(c1.x, qa1, accA[2 * kp]);
            accA[2 * kp + 1] = fma2(c1.y, qa1, accA[2 * kp + 1]);
            accB[2 * kp]     = fma2(c1.x, qb1, accB[2 * kp]);
            accB[2 * kp + 1] = fma2(c1.y, qb1, accB[2 * kp + 1]);
        }
    }

    // reduce across the 4 sub-lanes (offsets 1, 2)
    #pragma unroll
    for (int k = 0; k < KK; k++) {
        accA[k] = add2(accA[k], __shfl_xor_sync(0xffffffffu, accA[k], 1));
        accA[k] = add2(accA[k], __shfl_xor_sync(0xffffffffu, accA[k], 2));
        accB[k] = add2(accB[k], __shfl_xor_sync(0xffffffffu, accB[k], 1));
        accB[k] = add2(accB[k], __shfl_xor_sync(0xffffffffu, accB[k], 2));
    }
    S2A = add2(S2A, __shfl_xor_sync(0xffffffffu, S2A, 1));
    S2A = add2(S2A, __shfl_xor_sync(0xffffffffu, S2A, 2));
    S2B = add2(S2B, __shfl_xor_sync(0xffffffffu, S2B, 1));
    S2B = add2(S2B, __shfl_xor_sync(0xffffffffu, S2B, 2));

    if (s == 0) {
        if (rowA < nrows) {
            int f = finish_row(accA, S2A, s_C, rowA, out_logit, out_qy, out_ind);
            g_flag[rowA] = (!fast) | f;
        }
        if (rowB < nrows) {
            int f = finish_row(accB, S2B, s_C, rowB, out_logit, out_qy, out_ind);
            g_flag[rowB] = (!fast) | f;
        }
    }
}

// ================= kernel 2: exact fix (bitwise XLA:GPU order, proven) =================
__global__ void __launch_bounds__(128)
k_fix(const float* __restrict__ q, const float* __restrict__ mu,
      const float* __restrict__ lv,
      float* __restrict__ out_logit, float* __restrict__ out_qy,
      float* __restrict__ out_ind, int nrows)
{
    int lane = threadIdx.x & 31;
    int gw   = (blockIdx.x * blockDim.x + threadIdx.x) >> 5;
    int nw   = (gridDim.x * blockDim.x) >> 5;
    const float logk = (float)log((double)(1.0f / (float)KK));

    for (int base = gw * 32; base < nrows; base += nw * 32) {
        int rprobe = base + lane;
        int fl = (rprobe < nrows) ? g_flag[rprobe] : 0;
        unsigned mask = __ballot_sync(0xffffffffu, fl != 0);
        while (mask) {
            int b = __ffs(mask) - 1;
            mask &= mask - 1;
            int rr = base + b;

            float l10[KK];
            #pragma unroll 2
            for (int k = 0; k < KK; k++) {
                float W[4];
                #pragma unroll
                for (int j = 0; j < 4; j++) {
                    int d0 = 64 * j + 2 * lane;
                    float2 qq2 = *reinterpret_cast<const float2*>(q + (size_t)rr * DD + d0);
                    float m0 = mu[k * DD + d0], m1 = mu[k * DD + d0 + 1];
                    float v0 = lv[k * DD + d0], v1 = lv[k * DD + d0 + 1];
                    float e0 = (v0 == 0.0f) ? 1.0f : expf(v0);
                    float e1 = (v1 == 0.0f) ? 1.0f : expf(v1);
                    float f0 = __fadd_rn(qq2.x, -m0);
                    float f1 = __fadd_rn(qq2.y, -m1);
                    // u = fl(fl(fl(fl(diff^2)/e^lv)+lv)+L2PI); lv==0 -> fl(fl(d^2)+L2PI)
                    float u0 = __fadd_rn(__fadd_rn(__fdiv_rn(__fmul_rn(f0, f0), e0), v0), L2PI_F);
                    float u1 = __fadd_rn(__fadd_rn(__fdiv_rn(__fmul_rn(f1, f1), e1), v1), L2PI_F);
                    float ss = __fadd_rn(u0, u1);           // s_t = fl(u_even + u_odd)
                    ss = __fadd_rn(ss, __shfl_down_sync(0xffffffffu, ss, 16));
                    ss = __fadd_rn(ss, __shfl_down_sync(0xffffffffu, ss, 8));
                    ss = __fadd_rn(ss, __shfl_down_sync(0xffffffffu, ss, 4));
                    ss = __fadd_rn(ss, __shfl_down_sync(0xffffffffu, ss, 2));
                    ss = __fadd_rn(ss, __shfl_down_sync(0xffffffffu, ss, 1));
                    W[j] = __shfl_sync(0xffffffffu, ss, 0);
                }
                float L = __fadd_rn(__fadd_rn(W[0], W[2]), __fadd_rn(W[1], W[3]));
                l10[k] = __fadd_rn(__fmul_rn(-0.5f, L), logk);
            }
            if (lane == 0) {
                float m = l10[0];
                #pragma unroll
                for (int k = 1; k < KK; k++) m = fmaxf(m, l10[k]);
                float e[KK];
                #pragma unroll
                for (int k = 0; k < KK; k++) e[k] = expf(__fadd_rn(l10[k], -m));
                float s0 = __fadd_rn(__fadd_rn(__fadd_rn(e[0], e[8]), e[4]),
                                     __fadd_rn(e[2], e[6]));
                float s1 = __fadd_rn(__fadd_rn(__fadd_rn(e[1], e[9]), e[5]),
                                     __fadd_rn(e[3], e[7]));
                float ssum = __fadd_rn(s0, s1);
                float qv[KK];
                #pragma unroll
                for (int k = 0; k < KK; k++) qv[k] = __fdiv_rn(e[k], ssum);
                #pragma unroll
                for (int k = 0; k < KK; k++) {
                    out_logit[(size_t)rr * KK + k] = l10[k];
                    out_qy   [(size_t)rr * KK + k] = qv[k];
                }
                int best = 0; float bv = qv[0];
                #pragma unroll
                for (int k = 1; k < KK; k++)
                    if (qv[k] > bv) { bv = qv[k]; best = k; }
                out_ind[rr] = (float)best;
            }
        }
    }
}

extern "C" void kernel_launch(void* const* d_in, const int* in_sizes, int n_in,
                              void* d_out, int out_size) {
    const float* q_z = (const float*)d_in[0];   // [B, 256]
    const float* mu  = (const float*)d_in[1];   // [10, 256]
    const float* lv  = (const float*)d_in[2];   // [10, 256]

    int nrows = in_sizes[0] / DD;

    float* out_logit = (float*)d_out;                    // [B, 10]
    float* out_qy    = out_logit + (size_t)nrows * KK;   // [B, 10]
    float* out_ind   = out_qy    + (size_t)nrows * KK;   // [B]

    k_main<<<(nrows + RPB - 1) / RPB, 128>>>(q_z, mu, lv,
                                             out_logit, out_qy, out_ind, nrows);
    k_fix<<<512, 128>>>(q_z, mu, lv, out_logit, out_qy, out_ind, nrows);
}

// round 9
// speedup vs baseline: 1.3220x; 1.3220x over previous
#include <cuda_runtime.h>
#include <cstdint>
#include <math.h>

// Problem constants (dataset: B=65536, D=256, K=10)
#define KK 10
#define DD 256
#define RPB 64                // k_main: rows per block
#define FLAGCAP 65536
#define L2PI_F 1.8378770664093453f
#define MARGIN 0.03f

typedef unsigned long long ull;

// ---- device globals ----
__device__ int g_flag[FLAGCAP];

// ---------- packed f32x2 helpers ----------
static __device__ __forceinline__ ull pack2(float x, float y) {
    ull r; asm("mov.b64 %0, {%1, %2};" : "=l"(r) : "f"(x), "f"(y)); return r;
}
static __device__ __forceinline__ void unpack2(ull v, float& x, float& y) {
    asm("mov.b64 {%0, %1}, %2;" : "=f"(x), "=f"(y) : "l"(v));
}
static __device__ __forceinline__ ull fma2(ull a, ull b, ull c) {
    ull d; asm("fma.rn.f32x2 %0, %1, %2, %3;" : "=l"(d) : "l"(a), "l"(b), "l"(c)); return d;
}
static __device__ __forceinline__ ull add2(ull a, ull b) {
    ull d; asm("add.rn.f32x2 %0, %1, %2;" : "=l"(d) : "l"(a), "l"(b)); return d;
}
static __device__ __forceinline__ ull mul2(ull a, ull b) {
    ull d; asm("mul.rn.f32x2 %0, %1, %2;" : "=l"(d) : "l"(a), "l"(b)); return d;
}

// cheap finish for one row (tolerant path) — returns need-exact flag
static __device__ __forceinline__ int finish_row(
    const ull* acc, ull S2, const float* s_C, int row,
    float* out_logit, float* out_qy, float* out_ind)
{
    float s2f;
    { float lo, hi; unpack2(S2, lo, hi); s2f = lo + hi; }
    float l[KK];
    #pragma unroll
    for (int k = 0; k < KK; k++) {
        float lo, hi; unpack2(acc[k], lo, hi);
        l[k] = __fmaf_rn(-0.5f, (lo + hi) + s2f, s_C[k]);
    }
    float t1 = l[0], t2 = -3.4e38f;
    #pragma unroll
    for (int k = 1; k < KK; k++) {
        float v = l[k];
        if (v > t1) { t2 = t1; t1 = v; } else if (v > t2) t2 = v;
    }
    float e[KK], ssum = 0.0f;
    #pragma unroll
    for (int k = 0; k < KK; k++) { e[k] = __expf(l[k] - t1); ssum += e[k]; }
    float inv = 1.0f / ssum;

    float2* lo2 = reinterpret_cast<float2*>(out_logit + (size_t)row * KK);
    float2* qo2 = reinterpret_cast<float2*>(out_qy    + (size_t)row * KK);
    #pragma unroll
    for (int i = 0; i < KK / 2; i++) {
        lo2[i] = make_float2(l[2 * i], l[2 * i + 1]);
        qo2[i] = make_float2(e[2 * i] * inv, e[2 * i + 1] * inv);
    }
    int best = 0; float bv = l[0];
    #pragma unroll
    for (int k = 1; k < KK; k++) if (l[k] > bv) { bv = l[k]; best = k; }
    out_ind[row] = (float)best;
    return (t1 - t2 < MARGIN) ? 1 : 0;
}

// ========== kernel 1: cheap logits (R=2) + finish + flags — UNCHANGED (27us) ==========
__global__ void __launch_bounds__(128, 5)
k_main(const float* __restrict__ q, const float* __restrict__ mu,
       const float* __restrict__ lv,
       float* __restrict__ out_logit, float* __restrict__ out_qy,
       float* __restrict__ out_ind, int nrows)
{
    __shared__ __align__(16) ulonglong2 s_cb[640];
    __shared__ float s_Cpart[KK][8];
    __shared__ float s_C[KK];
    __shared__ int   s_nz;

    const int t = threadIdx.x;
    if (t == 0) s_nz = 0;
    __syncthreads();

    int any = 0;
    #pragma unroll
    for (int i = 0; i < 5; i++) {
        int e = t + 128 * i;
        int s  = e & 3;
        int rest = e >> 2;
        int kp = rest % 5;
        int gh = rest / 5;
        int h = gh & 1, g = gh >> 1;
        int pair = 8 * g + 2 * s + h, d = 2 * pair;
        int k0 = 2 * kp, k1 = 2 * kp + 1;
        float l00 = lv[k0 * DD + d], l01 = lv[k0 * DD + d + 1];
        float l10 = lv[k1 * DD + d], l11 = lv[k1 * DD + d + 1];
        float m00 = mu[k0 * DD + d], m01 = mu[k0 * DD + d + 1];
        float m10 = mu[k1 * DD + d], m11 = mu[k1 * DD + d + 1];
        ulonglong2 u;
        u.x = pack2(-2.0f * __expf(-l00) * m00, -2.0f * __expf(-l01) * m01);
        u.y = pack2(-2.0f * __expf(-l10) * m10, -2.0f * __expf(-l11) * m11);
        s_cb[e] = u;
        if (l00 != 0.0f || l01 != 0.0f || l10 != 0.0f || l11 != 0.0f) any = 1;
    }
    if (any) atomicOr(&s_nz, 1);
    if (t < 80) {
        int k = t >> 3, part = t & 7;
        float s = 0.0f;
        #pragma unroll 4
        for (int j = 0; j < 32; j++) {
            int d = part * 32 + j;
            float l = lv[k * DD + d], m = mu[k * DD + d];
            s += __fmaf_rn(__expf(-l) * m, m, l) + L2PI_F;
        }
        s_Cpart[k][part] = s;
    }
    __syncthreads();
    if (t < KK) {
        float tot = 0.0f;
        #pragma unroll
        for (int j = 0; j < 8; j++) tot += s_Cpart[t][j];
        float logk = (float)log((double)(1.0f / (float)KK));
        s_C[t] = __fmaf_rn(-0.5f, tot, logk);
    }
    __syncthreads();
    const int fast = (s_nz == 0);

    const int lane = t & 31, warp = t >> 5;
    const int s = lane & 3, r = lane >> 2;
    const int rowA = blockIdx.x * RPB + warp * 16 + r;
    const int rowB = rowA + 8;
    const int cA = (rowA < nrows) ? rowA : 0;
    const int cB = (rowB < nrows) ? rowB : 0;
    const float4* qpA = reinterpret_cast<const float4*>(q) + (size_t)cA * 64 + s;
    const float4* qpB = reinterpret_cast<const float4*>(q) + (size_t)cB * 64 + s;

    ull accA[KK], accB[KK];
    #pragma unroll
    for (int k = 0; k < KK; k++) { accA[k] = 0ull; accB[k] = 0ull; }
    ull S2A = 0ull, S2B = 0ull;

    float4 pA0 = __ldg(qpA),     pB0 = __ldg(qpB);
    float4 pA1 = __ldg(qpA + 4), pB1 = __ldg(qpB + 4);

    #pragma unroll
    for (int g = 0; g < 16; g++) {
        float4 vA = pA0, vB = pB0;
        pA0 = pA1; pB0 = pB1;
        if (g + 2 < 16) {
            pA1 = __ldg(qpA + 4 * (g + 2));
            pB1 = __ldg(qpB + 4 * (g + 2));
        }
        ull qa0 = pack2(vA.x, vA.y), qa1 = pack2(vA.z, vA.w);
        ull qb0 = pack2(vB.x, vB.y), qb1 = pack2(vB.z, vB.w);
        S2A = fma2(qa0, qa0, S2A); S2A = fma2(qa1, qa1, S2A);
        S2B = fma2(qb0, qb0, S2B); S2B = fma2(qb1, qb1, S2B);

        const int b0 = (2 * g) * 20 + s;
        const int b1 = (2 * g + 1) * 20 + s;
        #pragma unroll
        for (int kp = 0; kp < 5; kp++) {
            ulonglong2 c0 = s_cb[b0 + 4 * kp];
            accA[2 * kp]     = fma2(c0.x, qa0, accA[2 * kp]);
            accA[2 * kp + 1] = fma2(c0.y, qa0, accA[2 * kp + 1]);
            accB[2 * kp]     = fma2(c0.x, qb0, accB[2 * kp]);
            accB[2 * kp + 1] = fma2(c0.y, qb0, accB[2 * kp + 1]);
            ulonglong2 c1 = s_cb[b1 + 4 * kp];
            accA[2 * kp]     = fma2(c1.x, qa1, accA[2 * kp]);
            accA[2 * kp + 1] = fma2(c1.y, qa1, accA[2 * kp + 1]);
            accB[2 * kp]     = fma2(c1.x, qb1, accB[2 * kp]);
            accB[2 * kp + 1] = fma2(c1.y, qb1, accB[2 * kp + 1]);
        }
    }

    #pragma unroll
    for (int k = 0; k < KK; k++) {
        accA[k] = add2(accA[k], __shfl_xor_sync(0xffffffffu, accA[k], 1));
        accA[k] = add2(accA[k], __shfl_xor_sync(0xffffffffu, accA[k], 2));
        accB[k] = add2(accB[k], __shfl_xor_sync(0xffffffffu, accB[k], 1));
        accB[k] = add2(accB[k], __shfl_xor_sync(0xffffffffu, accB[k], 2));
    }
    S2A = add2(S2A, __shfl_xor_sync(0xffffffffu, S2A, 1));
    S2A = add2(S2A, __shfl_xor_sync(0xffffffffu, S2A, 2));
    S2B = add2(S2B, __shfl_xor_sync(0xffffffffu, S2B, 1));
    S2B = add2(S2B, __shfl_xor_sync(0xffffffffu, S2B, 2));

    if (s == 0) {
        if (rowA < nrows) {
            int f = finish_row(accA, S2A, s_C, rowA, out_logit, out_qy, out_ind);
            g_flag[rowA] = (!fast) | f;
        }
        if (rowB < nrows) {
            int f = finish_row(accB, S2B, s_C, rowB, out_logit, out_qy, out_ind);
            g_flag[rowB] = (!fast) | f;
        }
    }
}

// ========== kernel 2: exact fix — 1 thread/row, in-register XLA tree ==========
// Each warp scans 128 rows, compacts flagged into smem, processes 32 at a time.
#define FIXW 4                    // warps per fix block
__global__ void __launch_bounds__(32 * FIXW)
k_fix(const float* __restrict__ q, const float* __restrict__ mu,
      const float* __restrict__ lv,
      float* __restrict__ out_logit, float* __restrict__ out_qy,
      float* __restrict__ out_ind, int nrows)
{
    __shared__ __align__(16) ull s_nm[KK * 128];   // packed (-mu_d, -mu_{d+1})
    __shared__ __align__(16) ull s_lv[KK * 128];   // packed (lv_d, lv_{d+1})
    __shared__ int s_rows[FIXW][128];
    __shared__ int s_n[FIXW];
    __shared__ int s_nz;

    const int t = threadIdx.x;
    const int lane = t & 31, w = t >> 5;
    if (t == 0) s_nz = 0;
    __syncthreads();

    // stage -mu / lv packed (exact: sign flip only)
    int any = 0;
    for (int i = t; i < KK * 128; i += 32 * FIXW) {
        int k = i >> 7, p = i & 127, d = 2 * p;
        float m0 = mu[k * DD + d], m1 = mu[k * DD + d + 1];
        float l0 = lv[k * DD + d], l1 = lv[k * DD + d + 1];
        s_nm[i] = pack2(-m0, -m1);
        s_lv[i] = pack2(l0, l1);
        if (l0 != 0.0f || l1 != 0.0f) any = 1;
    }
    if (any) atomicOr(&s_nz, 1);
    if (lane == 0) s_n[w] = 0;
    __syncthreads();
    const int fastf = (s_nz == 0);

    // warp-level compaction of flagged rows (128 rows per warp)
    const int base = (blockIdx.x * FIXW + w) * 128;
    #pragma unroll
    for (int j = 0; j < 4; j++) {
        int rr = base + 32 * j + lane;
        int fl = (rr < nrows) ? g_flag[rr] : 0;
        unsigned m = __ballot_sync(0xffffffffu, fl != 0);
        int cnt = s_n[w];
        int pos = cnt + __popc(m & ((1u << lane) - 1u));
        if (fl) s_rows[w][pos] = rr;
        if (lane == 0) s_n[w] = cnt + __popc(m);
        __syncwarp();
    }
    int n = s_n[w];
    const float logk = (float)log((double)(1.0f / (float)KK));
    const ull L2 = pack2(L2PI_F, L2PI_F);

    for (int i0 = 0; i0 < n; i0 += 32) {
        int idx = i0 + lane;
        bool act = (idx < n);
        int rr = act ? s_rows[w][idx] : 0;

        float W[KK][4];
        #pragma unroll 1
        for (int k = 0; k < KK; k++) {
            #pragma unroll
            for (int w4 = 0; w4 < 4; w4++) {
                // load q chunk d = 64*w4 .. +63 as 32 packed pairs
                ull qp[32];
                const float4* q4 = reinterpret_cast<const float4*>(
                    q + (size_t)rr * DD + 64 * w4);
                #pragma unroll
                for (int j = 0; j < 16; j++) {
                    float4 v = __ldg(q4 + j);          // L1-hit after k=0
                    qp[2 * j]     = pack2(v.x, v.y);
                    qp[2 * j + 1] = pack2(v.z, v.w);
                }
                float a[16];
                if (fastf) {
                    #pragma unroll
                    for (int l = 0; l < 16; l++) {
                        int ib = k * 128 + w4 * 32;
                        ull f1 = add2(qp[l],      s_nm[ib + l]);       // fl(q-mu)
                        ull u1 = add2(mul2(f1, f1), L2);               // fl(d^2)+L2PI
                        ull f2 = add2(qp[l + 16], s_nm[ib + l + 16]);
                        ull u2 = add2(mul2(f2, f2), L2);
                        float x1, y1, x2, y2;
                        unpack2(u1, x1, y1); unpack2(u2, x2, y2);
                        // a_l = fl( s_l + s_{l+16} ), s = fl(u_even+u_odd)
                        a[l] = __fadd_rn(__fadd_rn(x1, y1), __fadd_rn(x2, y2));
                    }
                } else {
                    #pragma unroll
                    for (int l = 0; l < 16; l++) {
                        int ib = k * 128 + w4 * 32;
                        float s12[2];
                        #pragma unroll
                        for (int hh = 0; hh < 2; hh++) {
                            int ix = ib + l + 16 * hh;
                            float q0, q1, n0, n1, v0, v1;
                            unpack2(qp[l + 16 * hh], q0, q1);
                            unpack2(s_nm[ix], n0, n1);
                            unpack2(s_lv[ix], v0, v1);
                            float e0 = (v0 == 0.0f) ? 1.0f : expf(v0);
                            float e1 = (v1 == 0.0f) ? 1.0f : expf(v1);
                            float f0 = __fadd_rn(q0, n0), f1 = __fadd_rn(q1, n1);
                            float u0 = __fadd_rn(__fadd_rn(
                                __fdiv_rn(__fmul_rn(f0, f0), e0), v0), L2PI_F);
                            float u1 = __fadd_rn(__fadd_rn(
                                __fdiv_rn(__fmul_rn(f1, f1), e1), v1), L2PI_F);
                            s12[hh] = __fadd_rn(u0, u1);
                        }
                        a[l] = __fadd_rn(s12[0], s12[1]);
                    }
                }
                float b[8];
                #pragma unroll
                for (int l = 0; l < 8; l++) b[l] = __fadd_rn(a[l], a[l + 8]);
                float c[4];
                #pragma unroll
                for (int l = 0; l < 4; l++) c[l] = __fadd_rn(b[l], b[l + 4]);
                float d0 = __fadd_rn(c[0], c[2]);
                float d1 = __fadd_rn(c[1], c[3]);
                W[k][w4] = __fadd_rn(d0, d1);
            }
        }

        if (act) {
            float l10[KK];
            #pragma unroll
            for (int k = 0; k < KK; k++) {
                float L = __fadd_rn(__fadd_rn(W[k][0], W[k][2]),
                                    __fadd_rn(W[k][1], W[k][3]));
                l10[k] = __fadd_rn(__fmul_rn(-0.5f, L), logk);
            }
            float m = l10[0];
            #pragma unroll
            for (int k = 1; k < KK; k++) m = fmaxf(m, l10[k]);
            float e[KK];
            #pragma unroll
            for (int k = 0; k < KK; k++) e[k] = expf(__fadd_rn(l10[k], -m));
            float s0 = __fadd_rn(__fadd_rn(__fadd_rn(e[0], e[8]), e[4]),
                                 __fadd_rn(e[2], e[6]));
            float s1 = __fadd_rn(__fadd_rn(__fadd_rn(e[1], e[9]), e[5]),
                                 __fadd_rn(e[3], e[7]));
            float ssum = __fadd_rn(s0, s1);
            float qv[KK];
            #pragma unroll
            for (int k = 0; k < KK; k++) qv[k] = __fdiv_rn(e[k], ssum);
            #pragma unroll
            for (int k = 0; k < KK; k++) {
                out_logit[(size_t)rr * KK + k] = l10[k];
                out_qy   [(size_t)rr * KK + k] = qv[k];
            }
            int best = 0; float bv = qv[0];
            #pragma unroll
            for (int k = 1; k < KK; k++)
                if (qv[k] > bv) { bv = qv[k]; best = k; }
            out_ind[rr] = (float)best;
        }
    }
}

extern "C" void kernel_launch(void* const* d_in, const int* in_sizes, int n_in,
                              void* d_out, int out_size) {
    const float* q_z = (const float*)d_in[0];   // [B, 256]
    const float* mu  = (const float*)d_in[1];   // [10, 256]
    const float* lv  = (const float*)d_in[2];   // [10, 256]

    int nrows = in_sizes[0] / DD;

    float* out_logit = (float*)d_out;                    // [B, 10]
    float* out_qy    = out_logit + (size_t)nrows * KK;   // [B, 10]
    float* out_ind   = out_qy    + (size_t)nrows * KK;   // [B]

    k_main<<<(nrows + RPB - 1) / RPB, 128>>>(q_z, mu, lv,
                                             out_logit, out_qy, out_ind, nrows);
    int rows_per_fixblk = FIXW * 128;
    k_fix<<<(nrows + rows_per_fixblk - 1) / rows_per_fixblk, 32 * FIXW>>>(
        q_z, mu, lv, out_logit, out_qy, out_ind, nrows);
}

// round 10
// speedup vs baseline: 1.4652x; 1.1083x over previous
#include <cuda_runtime.h>
#include <cstdint>
#include <math.h>

// Problem constants (dataset: B=65536, D=256, K=10)
#define KK 10
#define DD 256
#define RPB 64                // k_main: rows per block
#define LISTCAP 65536
#define L2PI_F 1.8378770664093453f
#define MARGIN 0.03f

typedef unsigned long long ull;

// ---- device globals ----
__device__ int g_cnt;             // reset to 0 each run via cudaMemsetAsync
__device__ int g_list[LISTCAP];

// ---------- packed f32x2 helpers ----------
static __device__ __forceinline__ ull pack2(float x, float y) {
    ull r; asm("mov.b64 %0, {%1, %2};" : "=l"(r) : "f"(x), "f"(y)); return r;
}
static __device__ __forceinline__ void unpack2(ull v, float& x, float& y) {
    asm("mov.b64 {%0, %1}, %2;" : "=f"(x), "=f"(y) : "l"(v));
}
static __device__ __forceinline__ ull fma2(ull a, ull b, ull c) {
    ull d; asm("fma.rn.f32x2 %0, %1, %2, %3;" : "=l"(d) : "l"(a), "l"(b), "l"(c)); return d;
}
static __device__ __forceinline__ ull add2(ull a, ull b) {
    ull d; asm("add.rn.f32x2 %0, %1, %2;" : "=l"(d) : "l"(a), "l"(b)); return d;
}
static __device__ __forceinline__ ull mul2(ull a, ull b) {
    ull d; asm("mul.rn.f32x2 %0, %1, %2;" : "=l"(d) : "l"(a), "l"(b)); return d;
}

// cheap finish for one row (tolerant path) — returns need-exact flag
static __device__ __forceinline__ int finish_row(
    const ull* acc, ull S2, const float* s_C, int row,
    float* out_logit, float* out_qy, float* out_ind)
{
    float s2f;
    { float lo, hi; unpack2(S2, lo, hi); s2f = lo + hi; }
    float l[KK];
    #pragma unroll
    for (int k = 0; k < KK; k++) {
        float lo, hi; unpack2(acc[k], lo, hi);
        l[k] = __fmaf_rn(-0.5f, (lo + hi) + s2f, s_C[k]);
    }
    float t1 = l[0], t2 = -3.4e38f;
    #pragma unroll
    for (int k = 1; k < KK; k++) {
        float v = l[k];
        if (v > t1) { t2 = t1; t1 = v; } else if (v > t2) t2 = v;
    }
    float e[KK], ssum = 0.0f;
    #pragma unroll
    for (int k = 0; k < KK; k++) { e[k] = __expf(l[k] - t1); ssum += e[k]; }
    float inv = 1.0f / ssum;

    float2* lo2 = reinterpret_cast<float2*>(out_logit + (size_t)row * KK);
    float2* qo2 = reinterpret_cast<float2*>(out_qy    + (size_t)row * KK);
    #pragma unroll
    for (int i = 0; i < KK / 2; i++) {
        lo2[i] = make_float2(l[2 * i], l[2 * i + 1]);
        qo2[i] = make_float2(e[2 * i] * inv, e[2 * i + 1] * inv);
    }
    int best = 0; float bv = l[0];
    #pragma unroll
    for (int k = 1; k < KK; k++) if (l[k] > bv) { bv = l[k]; best = k; }
    out_ind[row] = (float)best;
    return (t1 - t2 < MARGIN) ? 1 : 0;
}

// ========== kernel 1: cheap logits (R=2) + finish + list append — core unchanged ======
__global__ void __launch_bounds__(128, 5)
k_main(const float* __restrict__ q, const float* __restrict__ mu,
       const float* __restrict__ lv,
       float* __restrict__ out_logit, float* __restrict__ out_qy,
       float* __restrict__ out_ind, int nrows)
{
    __shared__ __align__(16) ulonglong2 s_cb[640];
    __shared__ float s_Cpart[KK][8];
    __shared__ float s_C[KK];
    __shared__ int   s_nz;

    const int t = threadIdx.x;
    if (t == 0) s_nz = 0;
    __syncthreads();

    int any = 0;
    #pragma unroll
    for (int i = 0; i < 5; i++) {
        int e = t + 128 * i;
        int s  = e & 3;
        int rest = e >> 2;
        int kp = rest % 5;
        int gh = rest / 5;
        int h = gh & 1, g = gh >> 1;
        int pair = 8 * g + 2 * s + h, d = 2 * pair;
        int k0 = 2 * kp, k1 = 2 * kp + 1;
        float l00 = lv[k0 * DD + d], l01 = lv[k0 * DD + d + 1];
        float l10 = lv[k1 * DD + d], l11 = lv[k1 * DD + d + 1];
        float m00 = mu[k0 * DD + d], m01 = mu[k0 * DD + d + 1];
        float m10 = mu[k1 * DD + d], m11 = mu[k1 * DD + d + 1];
        ulonglong2 u;
        u.x = pack2(-2.0f * __expf(-l00) * m00, -2.0f * __expf(-l01) * m01);
        u.y = pack2(-2.0f * __expf(-l10) * m10, -2.0f * __expf(-l11) * m11);
        s_cb[e] = u;
        if (l00 != 0.0f || l01 != 0.0f || l10 != 0.0f || l11 != 0.0f) any = 1;
    }
    if (any) atomicOr(&s_nz, 1);
    if (t < 80) {
        int k = t >> 3, part = t & 7;
        float s = 0.0f;
        #pragma unroll 4
        for (int j = 0; j < 32; j++) {
            int d = part * 32 + j;
            float l = lv[k * DD + d], m = mu[k * DD + d];
            s += __fmaf_rn(__expf(-l) * m, m, l) + L2PI_F;
        }
        s_Cpart[k][part] = s;
    }
    __syncthreads();
    if (t < KK) {
        float tot = 0.0f;
        #pragma unroll
        for (int j = 0; j < 8; j++) tot += s_Cpart[t][j];
        float logk = (float)log((double)(1.0f / (float)KK));
        s_C[t] = __fmaf_rn(-0.5f, tot, logk);
    }
    __syncthreads();
    const int fast = (s_nz == 0);

    const int lane = t & 31, warp = t >> 5;
    const int s = lane & 3, r = lane >> 2;
    const int rowA = blockIdx.x * RPB + warp * 16 + r;
    const int rowB = rowA + 8;
    const int cA = (rowA < nrows) ? rowA : 0;
    const int cB = (rowB < nrows) ? rowB : 0;
    const float4* qpA = reinterpret_cast<const float4*>(q) + (size_t)cA * 64 + s;
    const float4* qpB = reinterpret_cast<const float4*>(q) + (size_t)cB * 64 + s;

    ull accA[KK], accB[KK];
    #pragma unroll
    for (int k = 0; k < KK; k++) { accA[k] = 0ull; accB[k] = 0ull; }
    ull S2A = 0ull, S2B = 0ull;

    float4 pA0 = __ldg(qpA),     pB0 = __ldg(qpB);
    float4 pA1 = __ldg(qpA + 4), pB1 = __ldg(qpB + 4);

    #pragma unroll
    for (int g = 0; g < 16; g++) {
        float4 vA = pA0, vB = pB0;
        pA0 = pA1; pB0 = pB1;
        if (g + 2 < 16) {
            pA1 = __ldg(qpA + 4 * (g + 2));
            pB1 = __ldg(qpB + 4 * (g + 2));
        }
        ull qa0 = pack2(vA.x, vA.y), qa1 = pack2(vA.z, vA.w);
        ull qb0 = pack2(vB.x, vB.y), qb1 = pack2(vB.z, vB.w);
        S2A = fma2(qa0, qa0, S2A); S2A = fma2(qa1, qa1, S2A);
        S2B = fma2(qb0, qb0, S2B); S2B = fma2(qb1, qb1, S2B);

        const int b0 = (2 * g) * 20 + s;
        const int b1 = (2 * g + 1) * 20 + s;
        #pragma unroll
        for (int kp = 0; kp < 5; kp++) {
            ulonglong2 c0 = s_cb[b0 + 4 * kp];
            accA[2 * kp]     = fma2(c0.x, qa0, accA[2 * kp]);
            accA[2 * kp + 1] = fma2(c0.y, qa0, accA[2 * kp + 1]);
            accB[2 * kp]     = fma2(c0.x, qb0, accB[2 * kp]);
            accB[2 * kp + 1] = fma2(c0.y, qb0, accB[2 * kp + 1]);
            ulonglong2 c1 = s_cb[b1 + 4 * kp];
            accA[2 * kp]     = fma2(c1.x, qa1, accA[2 * kp]);
            accA[2 * kp + 1] = fma2(c1.y, qa1, accA[2 * kp + 1]);
            accB[2 * kp]     = fma2(c1.x, qb1, accB[2 * kp]);
            accB[2 * kp + 1] = fma2(c1.y, qb1, accB[2 * kp + 1]);
        }
    }

    #pragma unroll
    for (int k = 0; k < KK; k++) {
        accA[k] = add2(accA[k], __shfl_xor_sync(0xffffffffu, accA[k], 1));
        accA[k] = add2(accA[k], __shfl_xor_sync(0xffffffffu, accA[k], 2));
        accB[k] = add2(accB[k], __shfl_xor_sync(0xffffffffu, accB[k], 1));
        accB[k] = add2(accB[k], __shfl_xor_sync(0xffffffffu, accB[k], 2));
    }
    S2A = add2(S2A, __shfl_xor_sync(0xffffffffu, S2A, 1));
    S2A = add2(S2A, __shfl_xor_sync(0xffffffffu, S2A, 2));
    S2B = add2(S2B, __shfl_xor_sync(0xffffffffu, S2B, 1));
    S2B = add2(S2B, __shfl_xor_sync(0xffffffffu, S2B, 2));

    if (s == 0) {
        if (rowA < nrows) {
            int f = finish_row(accA, S2A, s_C, rowA, out_logit, out_qy, out_ind);
            if ((!fast) | f) {
                int ix = atomicAdd(&g_cnt, 1);
                if (ix < LISTCAP) g_list[ix] = rowA;
            }
        }
        if (rowB < nrows) {
            int f = finish_row(accB, S2B, s_C, rowB, out_logit, out_qy, out_ind);
            if ((!fast) | f) {
                int ix = atomicAdd(&g_cnt, 1);
                if (ix < LISTCAP) g_list[ix] = rowB;
            }
        }
    }
}

// ========== kernel 2: exact fix — dense list, 1 thread/row, q loaded once ==========
__global__ void __launch_bounds__(128)
k_fix(const float* __restrict__ q, const float* __restrict__ mu,
      const float* __restrict__ lv,
      float* __restrict__ out_logit, float* __restrict__ out_qy,
      float* __restrict__ out_ind, int nrows)
{
    __shared__ __align__(16) ull s_nm[KK * 128];   // packed (-mu_d, -mu_{d+1})
    __shared__ __align__(16) ull s_lv[KK * 128];   // packed (lv_d, lv_{d+1})
    __shared__ int s_nz;

    const int t = threadIdx.x;
    const int lane = t & 31;
    if (t == 0) s_nz = 0;
    __syncthreads();

    int n = g_cnt; if (n > LISTCAP) n = LISTCAP;
    if (n == 0) return;

    // stage -mu / lv packed (exact: sign flip only)
    int any = 0;
    #pragma unroll
    for (int i = 0; i < KK; i++) {
        int ix = t + 128 * i;
        int k = ix >> 7, p = ix & 127, d = 2 * p;
        float m0 = mu[k * DD + d], m1 = mu[k * DD + d + 1];
        float l0 = lv[k * DD + d], l1 = lv[k * DD + d + 1];
        s_nm[ix] = pack2(-m0, -m1);
        s_lv[ix] = pack2(l0, l1);
        if (l0 != 0.0f || l1 != 0.0f) any = 1;
    }
    if (any) atomicOr(&s_nz, 1);
    __syncthreads();
    const int fastf = (s_nz == 0);

    const int gw = (blockIdx.x * blockDim.x + t) >> 5;
    const int nw = (gridDim.x * blockDim.x) >> 5;
    const float logk = (float)log((double)(1.0f / (float)KK));
    const ull L2 = pack2(L2PI_F, L2PI_F);

    for (int b = gw; b * 32 < n; b += nw) {
        int idx = b * 32 + lane;
        bool act = (idx < n);
        int rr = g_list[act ? idx : (n - 1)];

        float W[4][KK];
        #pragma unroll 1
        for (int w4 = 0; w4 < 4; w4++) {
            // load this row's 64-wide chunk ONCE (reused across all k)
            ull qp[32];
            const float4* q4 = reinterpret_cast<const float4*>(
                q + (size_t)rr * DD + 64 * w4);
            #pragma unroll
            for (int j = 0; j < 16; j++) {
                float4 v = __ldg(q4 + j);
                qp[2 * j]     = pack2(v.x, v.y);
                qp[2 * j + 1] = pack2(v.z, v.w);
            }

            #pragma unroll 1
            for (int k = 0; k < KK; k++) {
                const int ib = k * 128 + w4 * 32;
                float a[16];
                if (fastf) {
                    #pragma unroll
                    for (int l = 0; l < 16; l++) {
                        ull f1 = add2(qp[l],      s_nm[ib + l]);     // fl(q-mu)
                        ull u1 = add2(mul2(f1, f1), L2);             // fl(fl(d^2)+L2PI)
                        ull f2 = add2(qp[l + 16], s_nm[ib + l + 16]);
                        ull u2 = add2(mul2(f2, f2), L2);
                        float x1, y1, x2, y2;
                        unpack2(u1, x1, y1); unpack2(u2, x2, y2);
                        // a_l = fl( s_l + s_{l+16} ), s = fl(u_even + u_odd)
                        a[l] = __fadd_rn(__fadd_rn(x1, y1), __fadd_rn(x2, y2));
                    }
                } else {
                    #pragma unroll
                    for (int l = 0; l < 16; l++) {
                        float s12[2];
                        #pragma unroll
                        for (int hh = 0; hh < 2; hh++) {
                            int ix = ib + l + 16 * hh;
                            float q0, q1, n0, n1, v0, v1;
                            unpack2(qp[l + 16 * hh], q0, q1);
                            unpack2(s_nm[ix], n0, n1);
                            unpack2(s_lv[ix], v0, v1);
                            float e0 = (v0 == 0.0f) ? 1.0f : expf(v0);
                            float e1 = (v1 == 0.0f) ? 1.0f : expf(v1);
                            float f0 = __fadd_rn(q0, n0), f1 = __fadd_rn(q1, n1);
                            float u0 = __fadd_rn(__fadd_rn(
                                __fdiv_rn(__fmul_rn(f0, f0), e0), v0), L2PI_F);
                            float u1 = __fadd_rn(__fadd_rn(
                                __fdiv_rn(__fmul_rn(f1, f1), e1), v1), L2PI_F);
                            s12[hh] = __fadd_rn(u0, u1);
                        }
                        a[l] = __fadd_rn(s12[0], s12[1]);
                    }
                }
                float bb[8];
                #pragma unroll
                for (int l = 0; l < 8; l++) bb[l] = __fadd_rn(a[l], a[l + 8]);
                float cc[4];
                #pragma unroll
                for (int l = 0; l < 4; l++) cc[l] = __fadd_rn(bb[l], bb[l + 4]);
                float d0 = __fadd_rn(cc[0], cc[2]);
                float d1 = __fadd_rn(cc[1], cc[3]);
                W[w4][k] = __fadd_rn(d0, d1);
            }
        }

        if (act) {
            float l10[KK];
            #pragma unroll
            for (int k = 0; k < KK; k++) {
                float L = __fadd_rn(__fadd_rn(W[0][k], W[2][k]),
                                    __fadd_rn(W[1][k], W[3][k]));
                l10[k] = __fadd_rn(__fmul_rn(-0.5f, L), logk);
            }
            float m = l10[0];
            #pragma unroll
            for (int k = 1; k < KK; k++) m = fmaxf(m, l10[k]);
            float e[KK];
            #pragma unroll
            for (int k = 0; k < KK; k++) e[k] = expf(__fadd_rn(l10[k], -m));
            float s0 = __fadd_rn(__fadd_rn(__fadd_rn(e[0], e[8]), e[4]),
                                 __fadd_rn(e[2], e[6]));
            float s1 = __fadd_rn(__fadd_rn(__fadd_rn(e[1], e[9]), e[5]),
                                 __fadd_rn(e[3], e[7]));
            float ssum = __fadd_rn(s0, s1);
            float qv[KK];
            #pragma unroll
            for (int k = 0; k < KK; k++) qv[k] = __fdiv_rn(e[k], ssum);
            #pragma unroll
            for (int k = 0; k < KK; k++) {
                out_logit[(size_t)rr * KK + k] = l10[k];
                out_qy   [(size_t)rr * KK + k] = qv[k];
            }
            int best = 0; float bv = qv[0];
            #pragma unroll
            for (int k = 1; k < KK; k++)
                if (qv[k] > bv) { bv = qv[k]; best = k; }
            out_ind[rr] = (float)best;
        }
    }
}

extern "C" void kernel_launch(void* const* d_in, const int* in_sizes, int n_in,
                              void* d_out, int out_size) {
    const float* q_z = (const float*)d_in[0];   // [B, 256]
    const float* mu  = (const float*)d_in[1];   // [10, 256]
    const float* lv  = (const float*)d_in[2];   // [10, 256]

    int nrows = in_sizes[0] / DD;

    float* out_logit = (float*)d_out;                    // [B, 10]
    float* out_qy    = out_logit + (size_t)nrows * KK;   // [B, 10]
    float* out_ind   = out_qy    + (size_t)nrows * KK;   // [B]

    // reset flagged-row counter (graph-capturable memset node; no alloc, no sync)
    void* cnt_ptr = nullptr;
    cudaGetSymbolAddress(&cnt_ptr, g_cnt);
    cudaMemsetAsync(cnt_ptr, 0, sizeof(int));

    k_main<<<(nrows + RPB - 1) / RPB, 128>>>(q_z, mu, lv,
                                             out_logit, out_qy, out_ind, nrows);
    k_fix<<<148, 128>>>(q_z, mu, lv, out_logit, out_qy, out_ind, nrows);
}

// round 11
// speedup vs baseline: 1.5774x; 1.0766x over previous
#include <cuda_runtime.h>
#include <cstdint>
#include <math.h>

// Problem constants (dataset: B=65536, D=256, K=10)
#define KK 10
#define DD 256
#define RPB 64                // k_main: rows per block
#define LISTCAP 65536
#define L2PI_F 1.8378770664093453f
#define MARGIN 0.03f

typedef unsigned long long ull;

// ---- device globals ----
__device__ int g_cnt;             // reset each run via cudaMemsetAsync (graph node)
__device__ int g_list[LISTCAP];

// ---------- packed f32x2 helpers ----------
static __device__ __forceinline__ ull pack2(float x, float y) {
    ull r; asm("mov.b64 %0, {%1, %2};" : "=l"(r) : "f"(x), "f"(y)); return r;
}
static __device__ __forceinline__ void unpack2(ull v, float& x, float& y) {
    asm("mov.b64 {%0, %1}, %2;" : "=f"(x), "=f"(y) : "l"(v));
}
static __device__ __forceinline__ ull fma2(ull a, ull b, ull c) {
    ull d; asm("fma.rn.f32x2 %0, %1, %2, %3;" : "=l"(d) : "l"(a), "l"(b), "l"(c)); return d;
}
static __device__ __forceinline__ ull add2(ull a, ull b) {
    ull d; asm("add.rn.f32x2 %0, %1, %2;" : "=l"(d) : "l"(a), "l"(b)); return d;
}
static __device__ __forceinline__ ull mul2(ull a, ull b) {
    ull d; asm("mul.rn.f32x2 %0, %1, %2;" : "=l"(d) : "l"(a), "l"(b)); return d;
}

// cheap finish for one row (tolerant path) — returns need-exact flag
static __device__ __forceinline__ int finish_row(
    const ull* acc, ull S2, const float* s_C, int row,
    float* out_logit, float* out_qy, float* out_ind)
{
    float s2f;
    { float lo, hi; unpack2(S2, lo, hi); s2f = lo + hi; }
    float l[KK];
    #pragma unroll
    for (int k = 0; k < KK; k++) {
        float lo, hi; unpack2(acc[k], lo, hi);
        l[k] = __fmaf_rn(-0.5f, (lo + hi) + s2f, s_C[k]);
    }
    float t1 = l[0], t2 = -3.4e38f;
    #pragma unroll
    for (int k = 1; k < KK; k++) {
        float v = l[k];
        if (v > t1) { t2 = t1; t1 = v; } else if (v > t2) t2 = v;
    }
    float e[KK], ssum = 0.0f;
    #pragma unroll
    for (int k = 0; k < KK; k++) { e[k] = __expf(l[k] - t1); ssum += e[k]; }
    float inv = 1.0f / ssum;

    float2* lo2 = reinterpret_cast<float2*>(out_logit + (size_t)row * KK);
    float2* qo2 = reinterpret_cast<float2*>(out_qy    + (size_t)row * KK);
    #pragma unroll
    for (int i = 0; i < KK / 2; i++) {
        lo2[i] = make_float2(l[2 * i], l[2 * i + 1]);
        qo2[i] = make_float2(e[2 * i] * inv, e[2 * i + 1] * inv);
    }
    int best = 0; float bv = l[0];
    #pragma unroll
    for (int k = 1; k < KK; k++) if (l[k] > bv) { bv = l[k]; best = k; }
    out_ind[row] = (float)best;
    return (t1 - t2 < MARGIN) ? 1 : 0;
}

// ========== kernel 1: cheap logits (R=2) + finish + list append — UNCHANGED ==========
__global__ void __launch_bounds__(128, 5)
k_main(const float* __restrict__ q, const float* __restrict__ mu,
       const float* __restrict__ lv,
       float* __restrict__ out_logit, float* __restrict__ out_qy,
       float* __restrict__ out_ind, int nrows)
{
    __shared__ __align__(16) ulonglong2 s_cb[640];
    __shared__ float s_Cpart[KK][8];
    __shared__ float s_C[KK];
    __shared__ int   s_nz;

    const int t = threadIdx.x;
    if (t == 0) s_nz = 0;
    __syncthreads();

    int any = 0;
    #pragma unroll
    for (int i = 0; i < 5; i++) {
        int e = t + 128 * i;
        int s  = e & 3;
        int rest = e >> 2;
        int kp = rest % 5;
        int gh = rest / 5;
        int h = gh & 1, g = gh >> 1;
        int pair = 8 * g + 2 * s + h, d = 2 * pair;
        int k0 = 2 * kp, k1 = 2 * kp + 1;
        float l00 = lv[k0 * DD + d], l01 = lv[k0 * DD + d + 1];
        float l10 = lv[k1 * DD + d], l11 = lv[k1 * DD + d + 1];
        float m00 = mu[k0 * DD + d], m01 = mu[k0 * DD + d + 1];
        float m10 = mu[k1 * DD + d], m11 = mu[k1 * DD + d + 1];
        ulonglong2 u;
        u.x = pack2(-2.0f * __expf(-l00) * m00, -2.0f * __expf(-l01) * m01);
        u.y = pack2(-2.0f * __expf(-l10) * m10, -2.0f * __expf(-l11) * m11);
        s_cb[e] = u;
        if (l00 != 0.0f || l01 != 0.0f || l10 != 0.0f || l11 != 0.0f) any = 1;
    }
    if (any) atomicOr(&s_nz, 1);
    if (t < 80) {
        int k = t >> 3, part = t & 7;
        float s = 0.0f;
        #pragma unroll 4
        for (int j = 0; j < 32; j++) {
            int d = part * 32 + j;
            float l = lv[k * DD + d], m = mu[k * DD + d];
            s += __fmaf_rn(__expf(-l) * m, m, l) + L2PI_F;
        }
        s_Cpart[k][part] = s;
    }
    __syncthreads();
    if (t < KK) {
        float tot = 0.0f;
        #pragma unroll
        for (int j = 0; j < 8; j++) tot += s_Cpart[t][j];
        float logk = (float)log((double)(1.0f / (float)KK));
        s_C[t] = __fmaf_rn(-0.5f, tot, logk);
    }
    __syncthreads();
    const int fast = (s_nz == 0);

    const int lane = t & 31, warp = t >> 5;
    const int s = lane & 3, r = lane >> 2;
    const int rowA = blockIdx.x * RPB + warp * 16 + r;
    const int rowB = rowA + 8;
    const int cA = (rowA < nrows) ? rowA : 0;
    const int cB = (rowB < nrows) ? rowB : 0;
    const float4* qpA = reinterpret_cast<const float4*>(q) + (size_t)cA * 64 + s;
    const float4* qpB = reinterpret_cast<const float4*>(q) + (size_t)cB * 64 + s;

    ull accA[KK], accB[KK];
    #pragma unroll
    for (int k = 0; k < KK; k++) { accA[k] = 0ull; accB[k] = 0ull; }
    ull S2A = 0ull, S2B = 0ull;

    float4 pA0 = __ldg(qpA),     pB0 = __ldg(qpB);
    float4 pA1 = __ldg(qpA + 4), pB1 = __ldg(qpB + 4);

    #pragma unroll
    for (int g = 0; g < 16; g++) {
        float4 vA = pA0, vB = pB0;
        pA0 = pA1; pB0 = pB1;
        if (g + 2 < 16) {
            pA1 = __ldg(qpA + 4 * (g + 2));
            pB1 = __ldg(qpB + 4 * (g + 2));
        }
        ull qa0 = pack2(vA.x, vA.y), qa1 = pack2(vA.z, vA.w);
        ull qb0 = pack2(vB.x, vB.y), qb1 = pack2(vB.z, vB.w);
        S2A = fma2(qa0, qa0, S2A); S2A = fma2(qa1, qa1, S2A);
        S2B = fma2(qb0, qb0, S2B); S2B = fma2(qb1, qb1, S2B);

        const int b0 = (2 * g) * 20 + s;
        const int b1 = (2 * g + 1) * 20 + s;
        #pragma unroll
        for (int kp = 0; kp < 5; kp++) {
            ulonglong2 c0 = s_cb[b0 + 4 * kp];
            accA[2 * kp]     = fma2(c0.x, qa0, accA[2 * kp]);
            accA[2 * kp + 1] = fma2(c0.y, qa0, accA[2 * kp + 1]);
            accB[2 * kp]     = fma2(c0.x, qb0, accB[2 * kp]);
            accB[2 * kp + 1] = fma2(c0.y, qb0, accB[2 * kp + 1]);
            ulonglong2 c1 = s_cb[b1 + 4 * kp];
            accA[2 * kp]     = fma2(c1.x, qa1, accA[2 * kp]);
            accA[2 * kp + 1] = fma2(c1.y, qa1, accA[2 * kp + 1]);
            accB[2 * kp]     = fma2(c1.x, qb1, accB[2 * kp]);
            accB[2 * kp + 1] = fma2(c1.y, qb1, accB[2 * kp + 1]);
        }
    }

    #pragma unroll
    for (int k = 0; k < KK; k++) {
        accA[k] = add2(accA[k], __shfl_xor_sync(0xffffffffu, accA[k], 1));
        accA[k] = add2(accA[k], __shfl_xor_sync(0xffffffffu, accA[k], 2));
        accB[k] = add2(accB[k], __shfl_xor_sync(0xffffffffu, accB[k], 1));
        accB[k] = add2(accB[k], __shfl_xor_sync(0xffffffffu, accB[k], 2));
    }
    S2A = add2(S2A, __shfl_xor_sync(0xffffffffu, S2A, 1));
    S2A = add2(S2A, __shfl_xor_sync(0xffffffffu, S2A, 2));
    S2B = add2(S2B, __shfl_xor_sync(0xffffffffu, S2B, 1));
    S2B = add2(S2B, __shfl_xor_sync(0xffffffffu, S2B, 2));

    if (s == 0) {
        if (rowA < nrows) {
            int f = finish_row(accA, S2A, s_C, rowA, out_logit, out_qy, out_ind);
            if ((!fast) | f) {
                int ix = atomicAdd(&g_cnt, 1);
                if (ix < LISTCAP) g_list[ix] = rowA;
            }
        }
        if (rowB < nrows) {
            int f = finish_row(accB, S2B, s_C, rowB, out_logit, out_qy, out_ind);
            if ((!fast) | f) {
                int ix = atomicAdd(&g_cnt, 1);
                if (ix < LISTCAP) g_list[ix] = rowB;
            }
        }
    }
}

// ========== kernel 2: exact fix v4 — warp per row, lanes over (k,h) ==========
#define FIXWARPS 8
__global__ void __launch_bounds__(32 * FIXWARPS)
k_fix(const float* __restrict__ q, const float* __restrict__ mu,
      const float* __restrict__ lv,
      float* __restrict__ out_logit, float* __restrict__ out_qy,
      float* __restrict__ out_ind, int nrows)
{
    // k-interleaved tables: index p*KK + k (p = d-pair 0..127) -> conflict-free k-fan
    __shared__ __align__(16) ull s_nm[128 * KK];        // 10240 B
    __shared__ __align__(16) ull s_lv[128 * KK];        // 10240 B
    __shared__ __align__(16) ull s_q[FIXWARPS][128];    // 8192 B (1 row/warp)
    __shared__ int s_nz;

    const int t = threadIdx.x;
    const int lane = t & 31, w = t >> 5;
    if (t == 0) s_nz = 0;
    __syncthreads();

    int n = g_cnt; if (n > LISTCAP) n = LISTCAP;
    if (n == 0) return;

    // stage -mu / lv (exact: sign flip only)
    int any = 0;
    for (int i = t; i < 128 * KK; i += 32 * FIXWARPS) {
        int p = i / KK, k = i % KK, d = 2 * p;
        float m0 = mu[k * DD + d], m1 = mu[k * DD + d + 1];
        float l0 = lv[k * DD + d], l1 = lv[k * DD + d + 1];
        s_nm[i] = pack2(-m0, -m1);
        s_lv[i] = pack2(l0, l1);
        if (l0 != 0.0f || l1 != 0.0f) any = 1;
    }
    if (any) atomicOr(&s_nz, 1);
    __syncthreads();
    const int fastf = (s_nz == 0);

    const int gw = blockIdx.x * FIXWARPS + w;
    const int nw = gridDim.x * FIXWARPS;
    const float logk = (float)log((double)(1.0f / (float)KK));
    const ull L2 = pack2(L2PI_F, L2PI_F);

    const int kk = (lane < 20) ? (lane >> 1) : 0;   // component this lane owns
    const int h  = lane & 1;                        // w4 parity

    for (int i = gw; i < n; i += nw) {
        const int rr = g_list[i];

        // stage row q: coalesced, 2 float4 per lane -> packed pairs
        {
            const float4* q4 = reinterpret_cast<const float4*>(q + (size_t)rr * DD);
            float4 v0 = __ldg(q4 + lane);
            float4 v1 = __ldg(q4 + lane + 32);
            s_q[w][2 * lane]          = pack2(v0.x, v0.y);
            s_q[w][2 * lane + 1]      = pack2(v0.z, v0.w);
            s_q[w][2 * (lane + 32)]     = pack2(v1.x, v1.y);
            s_q[w][2 * (lane + 32) + 1] = pack2(v1.z, v1.w);
        }
        __syncwarp();

        // lane (kk,h): replay exact XLA tree for w4 = h and h+2
        float Wv[2];
        #pragma unroll
        for (int t2 = 0; t2 < 2; t2++) {
            const int w4 = h + 2 * t2;
            float a[16];
            if (fastf) {
                #pragma unroll
                for (int l = 0; l < 16; l++) {
                    int p1 = w4 * 32 + l, p2 = p1 + 16;
                    ull f1 = add2(s_q[w][p1], s_nm[p1 * KK + kk]);  // fl(q-mu)
                    ull u1 = add2(mul2(f1, f1), L2);                // fl(fl(d^2)+L2PI)
                    ull f2 = add2(s_q[w][p2], s_nm[p2 * KK + kk]);
                    ull u2 = add2(mul2(f2, f2), L2);
                    float x1, y1, x2, y2;
                    unpack2(u1, x1, y1); unpack2(u2, x2, y2);
                    // a_l = fl( s_l + s_{l+16} ), s = fl(u_even + u_odd)
                    a[l] = __fadd_rn(__fadd_rn(x1, y1), __fadd_rn(x2, y2));
                }
            } else {
                #pragma unroll
                for (int l = 0; l < 16; l++) {
                    float s12[2];
                    #pragma unroll
                    for (int hh = 0; hh < 2; hh++) {
                        int p = w4 * 32 + l + 16 * hh;
                        float q0, q1, n0, n1, v0, v1;
                        unpack2(s_q[w][p], q0, q1);
                        unpack2(s_nm[p * KK + kk], n0, n1);
                        unpack2(s_lv[p * KK + kk], v0, v1);
                        float e0 = (v0 == 0.0f) ? 1.0f : expf(v0);
                        float e1 = (v1 == 0.0f) ? 1.0f : expf(v1);
                        float f0 = __fadd_rn(q0, n0), f1 = __fadd_rn(q1, n1);
                        float u0 = __fadd_rn(__fadd_rn(
                            __fdiv_rn(__fmul_rn(f0, f0), e0), v0), L2PI_F);
                        float u1 = __fadd_rn(__fadd_rn(
                            __fdiv_rn(__fmul_rn(f1, f1), e1), v1), L2PI_F);
                        s12[hh] = __fadd_rn(u0, u1);
                    }
                    a[l] = __fadd_rn(s12[0], s12[1]);
                }
            }
            float bb[8];
            #pragma unroll
            for (int l = 0; l < 8; l++) bb[l] = __fadd_rn(a[l], a[l + 8]);
            float cc[4];
            #pragma unroll
            for (int l = 0; l < 4; l++) cc[l] = __fadd_rn(bb[l], bb[l + 4]);
            float d0 = __fadd_rn(cc[0], cc[2]);
            float d1 = __fadd_rn(cc[1], cc[3]);
            Wv[t2] = __fadd_rn(d0, d1);
        }
        // h=0: fl(W0+W2) ; h=1: fl(W1+W3)
        float sum2 = __fadd_rn(Wv[0], Wv[1]);
        float s_other = __shfl_down_sync(0xffffffffu, sum2, 1);
        float L = __fadd_rn(sum2, s_other);                 // valid at even lanes
        float lgt = __fadd_rn(__fmul_rn(-0.5f, L), logk);

        // gather all 10 logits to every lane
        float l10[KK];
        #pragma unroll
        for (int k = 0; k < KK; k++)
            l10[k] = __shfl_sync(0xffffffffu, lgt, 2 * k);

        if (lane == 0) {
            // exact round-3 finish
            float m = l10[0];
            #pragma unroll
            for (int k = 1; k < KK; k++) m = fmaxf(m, l10[k]);
            float e[KK];
            #pragma unroll
            for (int k = 0; k < KK; k++) e[k] = expf(__fadd_rn(l10[k], -m));
            float s0 = __fadd_rn(__fadd_rn(__fadd_rn(e[0], e[8]), e[4]),
                                 __fadd_rn(e[2], e[6]));
            float s1 = __fadd_rn(__fadd_rn(__fadd_rn(e[1], e[9]), e[5]),
                                 __fadd_rn(e[3], e[7]));
            float ssum = __fadd_rn(s0, s1);
            float qv[KK];
            #pragma unroll
            for (int k = 0; k < KK; k++) qv[k] = __fdiv_rn(e[k], ssum);
            #pragma unroll
            for (int k = 0; k < KK; k++) {
                out_logit[(size_t)rr * KK + k] = l10[k];
                out_qy   [(size_t)rr * KK + k] = qv[k];
            }
            int best = 0; float bv = qv[0];
            #pragma unroll
            for (int k = 1; k < KK; k++)
                if (qv[k] > bv) { bv = qv[k]; best = k; }
            out_ind[rr] = (float)best;
        }
        __syncwarp();
    }
}

extern "C" void kernel_launch(void* const* d_in, const int* in_sizes, int n_in,
                              void* d_out, int out_size) {
    const float* q_z = (const float*)d_in[0];   // [B, 256]
    const float* mu  = (const float*)d_in[1];   // [10, 256]
    const float* lv  = (const float*)d_in[2];   // [10, 256]

    int nrows = in_sizes[0] / DD;

    float* out_logit = (float*)d_out;                    // [B, 10]
    float* out_qy    = out_logit + (size_t)nrows * KK;   // [B, 10]
    float* out_ind   = out_qy    + (size_t)nrows * KK;   // [B]

    // reset flagged-row counter (graph-capturable memset node; no alloc, no sync)
    void* cnt_ptr = nullptr;
    cudaGetSymbolAddress(&cnt_ptr, g_cnt);
    cudaMemsetAsync(cnt_ptr, 0, sizeof(int));

    k_main<<<(nrows + RPB - 1) / RPB, 128>>>(q_z, mu, lv,
                                             out_logit, out_qy, out_ind, nrows);
    k_fix<<<148, 32 * FIXWARPS>>>(q_z, mu, lv, out_logit, out_qy, out_ind, nrows);
}

// round 12
// speedup vs baseline: 2.0498x; 1.2994x over previous
#include <cuda_runtime.h>
#include <cstdint>
#include <math.h>

// Problem constants (dataset: B=65536, D=256, K=10)
#define KK 10
#define DD 256
#define TROWS 128             // k_main: rows per tile (one block-iteration)
#define GRID_MAIN 444         // 3 blocks/SM * 148 SMs -> single persistent wave
#define FIXWARPS 8
#define GRID_FIX 444
#define LISTCAP 65536
#define L2PI_F 1.8378770664093453f
#define MARGIN 0.02f

typedef unsigned long long ull;

// ---- device globals ----
__device__ int g_ctrl[2];         // [0]=flag count, [1]=tile counter; memset each run
__device__ int g_list[LISTCAP];

// ---------- packed f32x2 helpers ----------
static __device__ __forceinline__ ull pack2(float x, float y) {
    ull r; asm("mov.b64 %0, {%1, %2};" : "=l"(r) : "f"(x), "f"(y)); return r;
}
static __device__ __forceinline__ void unpack2(ull v, float& x, float& y) {
    asm("mov.b64 {%0, %1}, %2;" : "=f"(x), "=f"(y) : "l"(v));
}
static __device__ __forceinline__ ull fma2(ull a, ull b, ull c) {
    ull d; asm("fma.rn.f32x2 %0, %1, %2, %3;" : "=l"(d) : "l"(a), "l"(b), "l"(c)); return d;
}
static __device__ __forceinline__ ull add2(ull a, ull b) {
    ull d; asm("add.rn.f32x2 %0, %1, %2;" : "=l"(d) : "l"(a), "l"(b)); return d;
}
static __device__ __forceinline__ ull mul2(ull a, ull b) {
    ull d; asm("mul.rn.f32x2 %0, %1, %2;" : "=l"(d) : "l"(a), "l"(b)); return d;
}

// cheap finish for one row (tolerant path)
static __device__ __forceinline__ void finish_row(
    const ull* acc, ull S2, const float* s_C, int row, int fast,
    float* out_logit, float* out_qy, float* out_ind)
{
    float s2f;
    { float lo, hi; unpack2(S2, lo, hi); s2f = lo + hi; }
    float l[KK];
    #pragma unroll
    for (int k = 0; k < KK; k++) {
        float lo, hi; unpack2(acc[k], lo, hi);
        l[k] = __fmaf_rn(-0.5f, (lo + hi) + s2f, s_C[k]);
    }
    float t1 = l[0], t2 = -3.4e38f;
    #pragma unroll
    for (int k = 1; k < KK; k++) {
        float v = l[k];
        if (v > t1) { t2 = t1; t1 = v; } else if (v > t2) t2 = v;
    }
    float e[KK], ssum = 0.0f;
    #pragma unroll
    for (int k = 0; k < KK; k++) { e[k] = __expf(l[k] - t1); ssum += e[k]; }
    float inv = 1.0f / ssum;

    float2* lo2 = reinterpret_cast<float2*>(out_logit + (size_t)row * KK);
    float2* qo2 = reinterpret_cast<float2*>(out_qy    + (size_t)row * KK);
    #pragma unroll
    for (int i = 0; i < KK / 2; i++) {
        lo2[i] = make_float2(l[2 * i], l[2 * i + 1]);
        qo2[i] = make_float2(e[2 * i] * inv, e[2 * i + 1] * inv);
    }
    int best = 0; float bv = l[0];
    #pragma unroll
    for (int k = 1; k < KK; k++) if (l[k] > bv) { bv = l[k]; best = k; }
    out_ind[row] = (float)best;

    if ((!fast) | (t1 - t2 < MARGIN)) {
        int ix = atomicAdd(&g_ctrl[0], 1);
        if (ix < LISTCAP) g_list[ix] = row;
    }
}

// ===== kernel 1: persistent, R=4 (4 rows/thread, 4 lanes/row), cheap logits =====
__global__ void __launch_bounds__(128, 3)
k_main(const float* __restrict__ q, const float* __restrict__ mu,
       const float* __restrict__ lv,
       float* __restrict__ out_logit, float* __restrict__ out_qy,
       float* __restrict__ out_ind, int nrows)
{
    __shared__ __align__(16) ulonglong2 s_cb[640];   // 10240 B
    __shared__ float s_Cpart[KK][8];
    __shared__ float s_C[KK];
    __shared__ int   s_nz;
    __shared__ int   s_tile;

    const int t = threadIdx.x;
    if (t == 0) s_nz = 0;
    __syncthreads();

    // ---- per-block prep (cheap __expf; exact when lv==0) ----
    int any = 0;
    #pragma unroll
    for (int i = 0; i < 5; i++) {
        int e = t + 128 * i;
        int s  = e & 3;
        int rest = e >> 2;
        int kp = rest % 5;
        int gh = rest / 5;
        int h = gh & 1, g = gh >> 1;
        int pair = 8 * g + 2 * s + h, d = 2 * pair;
        int k0 = 2 * kp, k1 = 2 * kp + 1;
        float l00 = lv[k0 * DD + d], l01 = lv[k0 * DD + d + 1];
        float l10 = lv[k1 * DD + d], l11 = lv[k1 * DD + d + 1];
        float m00 = mu[k0 * DD + d], m01 = mu[k0 * DD + d + 1];
        float m10 = mu[k1 * DD + d], m11 = mu[k1 * DD + d + 1];
        ulonglong2 u;
        u.x = pack2(-2.0f * __expf(-l00) * m00, -2.0f * __expf(-l01) * m01);
        u.y = pack2(-2.0f * __expf(-l10) * m10, -2.0f * __expf(-l11) * m11);
        s_cb[e] = u;
        if (l00 != 0.0f || l01 != 0.0f || l10 != 0.0f || l11 != 0.0f) any = 1;
    }
    if (any) atomicOr(&s_nz, 1);
    if (t < 80) {
        int k = t >> 3, part = t & 7;
        float s = 0.0f;
        #pragma unroll 4
        for (int j = 0; j < 32; j++) {
            int d = part * 32 + j;
            float l = lv[k * DD + d], m = mu[k * DD + d];
            s += __fmaf_rn(__expf(-l) * m, m, l) + L2PI_F;
        }
        s_Cpart[k][part] = s;
    }
    __syncthreads();
    if (t < KK) {
        float tot = 0.0f;
        #pragma unroll
        for (int j = 0; j < 8; j++) tot += s_Cpart[t][j];
        float logk = (float)log((double)(1.0f / (float)KK));
        s_C[t] = __fmaf_rn(-0.5f, tot, logk);
    }
    __syncthreads();
    const int fast = (s_nz == 0);

    const int lane = t & 31, warp = t >> 5;
    const int s = lane & 3, r = lane >> 2;           // lane sub / row-slot
    const int nt = (nrows + TROWS - 1) / TROWS;

    for (;;) {
        if (t == 0) s_tile = atomicAdd(&g_ctrl[1], 1);
        __syncthreads();
        const int tile = s_tile;
        __syncthreads();
        if (tile >= nt) break;

        const int row0 = tile * TROWS + warp * 32 + r;   // rows: row0 + 8*j
        const float4* qp[4];
        #pragma unroll
        for (int j = 0; j < 4; j++) {
            int rj = row0 + 8 * j;
            qp[j] = reinterpret_cast<const float4*>(q)
                  + (size_t)((rj < nrows) ? rj : 0) * 64 + s;
        }

        ull acc[4][KK];
        ull S2[4];
        #pragma unroll
        for (int j = 0; j < 4; j++) {
            S2[j] = 0ull;
            #pragma unroll
            for (int k = 0; k < KK; k++) acc[j][k] = 0ull;
        }

        float4 pv[4];
        #pragma unroll
        for (int j = 0; j < 4; j++) pv[j] = __ldg(qp[j]);   // g = 0

        #pragma unroll
        for (int g = 0; g < 16; g++) {
            float4 cv[4];
            #pragma unroll
            for (int j = 0; j < 4; j++) cv[j] = pv[j];
            if (g + 1 < 16) {
                #pragma unroll
                for (int j = 0; j < 4; j++) pv[j] = __ldg(qp[j] + 4 * (g + 1));
            }
            ull qa[4][2];
            #pragma unroll
            for (int j = 0; j < 4; j++) {
                qa[j][0] = pack2(cv[j].x, cv[j].y);
                qa[j][1] = pack2(cv[j].z, cv[j].w);
                S2[j] = fma2(qa[j][0], qa[j][0], S2[j]);
                S2[j] = fma2(qa[j][1], qa[j][1], S2[j]);
            }
            const int b0 = (2 * g) * 20 + s;       // ((2g+h)*5+kp)*4+s, h=0
            const int b1 = (2 * g + 1) * 20 + s;   // h=1
            #pragma unroll
            for (int kp = 0; kp < 5; kp++) {
                ulonglong2 c0 = s_cb[b0 + 4 * kp];
                #pragma unroll
                for (int j = 0; j < 4; j++) {
                    acc[j][2 * kp]     = fma2(c0.x, qa[j][0], acc[j][2 * kp]);
                    acc[j][2 * kp + 1] = fma2(c0.y, qa[j][0], acc[j][2 * kp + 1]);
                }
                ulonglong2 c1 = s_cb[b1 + 4 * kp];
                #pragma unroll
                for (int j = 0; j < 4; j++) {
                    acc[j][2 * kp]     = fma2(c1.x, qa[j][1], acc[j][2 * kp]);
                    acc[j][2 * kp + 1] = fma2(c1.y, qa[j][1], acc[j][2 * kp + 1]);
                }
            }
        }

        // reduce across the 4 sub-lanes of each row (offsets 1, 2)
        #pragma unroll
        for (int j = 0; j < 4; j++) {
            #pragma unroll
            for (int k = 0; k < KK; k++) {
                acc[j][k] = add2(acc[j][k], __shfl_xor_sync(0xffffffffu, acc[j][k], 1));
                acc[j][k] = add2(acc[j][k], __shfl_xor_sync(0xffffffffu, acc[j][k], 2));
            }
            S2[j] = add2(S2[j], __shfl_xor_sync(0xffffffffu, S2[j], 1));
            S2[j] = add2(S2[j], __shfl_xor_sync(0xffffffffu, S2[j], 2));
        }

        if (s == 0) {
            #pragma unroll
            for (int j = 0; j < 4; j++) {
                int rj = row0 + 8 * j;
                if (rj < nrows)
                    finish_row(acc[j], S2[j], s_C, rj, fast,
                               out_logit, out_qy, out_ind);
            }
        }
        __syncthreads();   // protect s_tile for next iteration
    }
}

// ========== kernel 2: exact fix — warp per row, lanes over (k,h) ==========
__global__ void __launch_bounds__(32 * FIXWARPS)
k_fix(const float* __restrict__ q, const float* __restrict__ mu,
      const float* __restrict__ lv,
      float* __restrict__ out_logit, float* __restrict__ out_qy,
      float* __restrict__ out_ind, int nrows)
{
    __shared__ __align__(16) ull s_nm[128 * KK];        // k-interleaved: p*KK+k
    __shared__ __align__(16) ull s_lv[128 * KK];
    __shared__ __align__(16) ull s_q[FIXWARPS][128];
    __shared__ int s_nz;

    int n = g_ctrl[0]; if (n > LISTCAP) n = LISTCAP;
    if (blockIdx.x * FIXWARPS >= n) return;             // no work for this block

    const int t = threadIdx.x;
    const int lane = t & 31, w = t >> 5;
    if (t == 0) s_nz = 0;
    __syncthreads();

    int any = 0;
    for (int i = t; i < 128 * KK; i += 32 * FIXWARPS) {
        int p = i / KK, k = i % KK, d = 2 * p;
        float m0 = mu[k * DD + d], m1 = mu[k * DD + d + 1];
        float l0 = lv[k * DD + d], l1 = lv[k * DD + d + 1];
        s_nm[i] = pack2(-m0, -m1);
        s_lv[i] = pack2(l0, l1);
        if (l0 != 0.0f || l1 != 0.0f) any = 1;
    }
    if (any) atomicOr(&s_nz, 1);
    __syncthreads();
    const int fastf = (s_nz == 0);

    const int gw = blockIdx.x * FIXWARPS + w;
    const int nw = GRID_FIX * FIXWARPS;
    const float logk = (float)log((double)(1.0f / (float)KK));
    const ull L2 = pack2(L2PI_F, L2PI_F);

    const int kk = (lane < 20) ? (lane >> 1) : 0;
    const int h  = lane & 1;

    for (int i = gw; i < n; i += nw) {
        const int rr = g_list[i];

        {   // stage row q: coalesced, 2 float4 per lane
            const float4* q4 = reinterpret_cast<const float4*>(q + (size_t)rr * DD);
            float4 v0 = __ldg(q4 + lane);
            float4 v1 = __ldg(q4 + lane + 32);
            s_q[w][2 * lane]            = pack2(v0.x, v0.y);
            s_q[w][2 * lane + 1]        = pack2(v0.z, v0.w);
            s_q[w][2 * (lane + 32)]     = pack2(v1.x, v1.y);
            s_q[w][2 * (lane + 32) + 1] = pack2(v1.z, v1.w);
        }
        __syncwarp();

        // lane (kk,h): replay exact XLA tree for w4 = h, h+2
        float Wv[2];
        #pragma unroll
        for (int t2 = 0; t2 < 2; t2++) {
            const int w4 = h + 2 * t2;
            float a[16];
            if (fastf) {
                #pragma unroll
                for (int l = 0; l < 16; l++) {
                    int p1 = w4 * 32 + l, p2 = p1 + 16;
                    ull f1 = add2(s_q[w][p1], s_nm[p1 * KK + kk]);  // fl(q-mu)
                    ull u1 = add2(mul2(f1, f1), L2);                // fl(fl(d^2)+L2PI)
                    ull f2 = add2(s_q[w][p2], s_nm[p2 * KK + kk]);
                    ull u2 = add2(mul2(f2, f2), L2);
                    float x1, y1, x2, y2;
                    unpack2(u1, x1, y1); unpack2(u2, x2, y2);
                    a[l] = __fadd_rn(__fadd_rn(x1, y1), __fadd_rn(x2, y2));
                }
            } else {
                #pragma unroll
                for (int l = 0; l < 16; l++) {
                    float s12[2];
                    #pragma unroll
                    for (int hh = 0; hh < 2; hh++) {
                        int p = w4 * 32 + l + 16 * hh;
                        float q0, q1, n0, n1, v0, v1;
                        unpack2(s_q[w][p], q0, q1);
                        unpack2(s_nm[p * KK + kk], n0, n1);
                        unpack2(s_lv[p * KK + kk], v0, v1);
                        float e0 = (v0 == 0.0f) ? 1.0f : expf(v0);
                        float e1 = (v1 == 0.0f) ? 1.0f : expf(v1);
                        float f0 = __fadd_rn(q0, n0), f1 = __fadd_rn(q1, n1);
                        float u0 = __fadd_rn(__fadd_rn(
                            __fdiv_rn(__fmul_rn(f0, f0), e0), v0), L2PI_F);
                        float u1 = __fadd_rn(__fadd_rn(
                            __fdiv_rn(__fmul_rn(f1, f1), e1), v1), L2PI_F);
                        s12[hh] = __fadd_rn(u0, u1);
                    }
                    a[l] = __fadd_rn(s12[0], s12[1]);
                }
            }
            float bb[8];
            #pragma unroll
            for (int l = 0; l < 8; l++) bb[l] = __fadd_rn(a[l], a[l + 8]);
            float cc[4];
            #pragma unroll
            for (int l = 0; l < 4; l++) cc[l] = __fadd_rn(bb[l], bb[l + 4]);
            float d0 = __fadd_rn(cc[0], cc[2]);
            float d1 = __fadd_rn(cc[1], cc[3]);
            Wv[t2] = __fadd_rn(d0, d1);
        }
        float sum2 = __fadd_rn(Wv[0], Wv[1]);              // h=0: W0+W2 ; h=1: W1+W3
        float s_other = __shfl_down_sync(0xffffffffu, sum2, 1);
        float L = __fadd_rn(sum2, s_other);                // valid at even lanes
        float lgt = __fadd_rn(__fmul_rn(-0.5f, L), logk);

        float l10[KK];
        #pragma unroll
        for (int k = 0; k < KK; k++)
            l10[k] = __shfl_sync(0xffffffffu, lgt, 2 * k);

        if (lane == 0) {
            float m = l10[0];
            #pragma unroll
            for (int k = 1; k < KK; k++) m = fmaxf(m, l10[k]);
            float e[KK];
            #pragma unroll
            for (int k = 0; k < KK; k++) e[k] = expf(__fadd_rn(l10[k], -m));
            float s0 = __fadd_rn(__fadd_rn(__fadd_rn(e[0], e[8]), e[4]),
                                 __fadd_rn(e[2], e[6]));
            float s1 = __fadd_rn(__fadd_rn(__fadd_rn(e[1], e[9]), e[5]),
                                 __fadd_rn(e[3], e[7]));
            float ssum = __fadd_rn(s0, s1);
            float qv[KK];
            #pragma unroll
            for (int k = 0; k < KK; k++) qv[k] = __fdiv_rn(e[k], ssum);
            #pragma unroll
            for (int k = 0; k < KK; k++) {
                out_logit[(size_t)rr * KK + k] = l10[k];
                out_qy   [(size_t)rr * KK + k] = qv[k];
            }
            int best = 0; float bv = qv[0];
            #pragma unroll
            for (int k = 1; k < KK; k++)
                if (qv[k] > bv) { bv = qv[k]; best = k; }
            out_ind[rr] = (float)best;
        }
        __syncwarp();
    }
}

extern "C" void kernel_launch(void* const* d_in, const int* in_sizes, int n_in,
                              void* d_out, int out_size) {
    const float* q_z = (const float*)d_in[0];   // [B, 256]
    const float* mu  = (const float*)d_in[1];   // [10, 256]
    const float* lv  = (const float*)d_in[2];   // [10, 256]

    int nrows = in_sizes[0] / DD;

    float* out_logit = (float*)d_out;                    // [B, 10]
    float* out_qy    = out_logit + (size_t)nrows * KK;   // [B, 10]
    float* out_ind   = out_qy    + (size_t)nrows * KK;   // [B]

    // reset flag counter + tile counter (one graph-capturable memset node)
    void* ctrl_ptr = nullptr;
    cudaGetSymbolAddress(&ctrl_ptr, g_ctrl);
    cudaMemsetAsync(ctrl_ptr, 0, 2 * sizeof(int));

    k_main<<<GRID_MAIN, 128>>>(q_z, mu, lv, out_logit, out_qy, out_ind, nrows);
    k_fix<<<GRID_FIX, 32 * FIXWARPS>>>(q_z, mu, lv, out_logit, out_qy, out_ind, nrows);
}